// round 13
// baseline (speedup 1.0000x reference)
#include <cuda_runtime.h>
#include <math.h>
#include <stdint.h>

#define D_EMBED 1024
#define SEQ     2048
#define BATCH   2
#define NHEAD   16
#define HDIM    64
#define NTOK    (BATCH * SEQ)      // 4096
#define LORA_R  8
#define LORA_SCALE_C 2.0f          // alpha/r = 16/8

// ---------------- scratch (no allocations allowed) ----------------
__device__ float g_qkv[(size_t)NTOK * 3 * D_EMBED];   // [B,S,3,H,hd] (roped+rounded)
__device__ float g_attn[(size_t)NTOK * D_EMBED];      // attention out (tf32-rounded)
__device__ float g_xa[(size_t)NTOK * LORA_R];         // x @ A^T
__device__ float g_xr[(size_t)NTOK * D_EMBED];        // tf32-rounded x
__device__ float g_wqr[(size_t)3 * D_EMBED * D_EMBED];// tf32-rounded Wqkv
__device__ float g_wpr[(size_t)D_EMBED * D_EMBED];    // tf32-rounded Wproj

// ---------------- helpers ----------------
__device__ __forceinline__ uint32_t f2tf(float x) {
    uint32_t u; asm("cvt.rna.tf32.f32 %0, %1;" : "=r"(u) : "f"(x)); return u;
}
__device__ __forceinline__ float f2tf_f(float x) {
    return __uint_as_float(f2tf(x));
}
__device__ __forceinline__ void mma_tf32(float c[4],
                                         uint32_t a0, uint32_t a1, uint32_t a2, uint32_t a3,
                                         uint32_t b0, uint32_t b1) {
    asm volatile(
        "mma.sync.aligned.m16n8k8.row.col.f32.tf32.tf32.f32 "
        "{%0,%1,%2,%3}, {%4,%5,%6,%7}, {%8,%9}, {%0,%1,%2,%3};"
        : "+f"(c[0]), "+f"(c[1]), "+f"(c[2]), "+f"(c[3])
        : "r"(a0), "r"(a1), "r"(a2), "r"(a3), "r"(b0), "r"(b1));
}
__device__ __forceinline__ void cp16(float* dst_smem, const float* src) {
    uint32_t d = (uint32_t)__cvta_generic_to_shared(dst_smem);
    asm volatile("cp.async.cg.shared.global [%0], [%1], 16;" :: "r"(d), "l"(src));
}
#define CP_COMMIT() asm volatile("cp.async.commit_group;")
#define CP_WAIT0()  asm volatile("cp.async.wait_group 0;")

// ---------------- tf32 pre-round (weights) ----------------
__global__ void round_tf32_kernel(const float4* __restrict__ in,
                                  float4* __restrict__ out, int n4) {
    int i = blockIdx.x * blockDim.x + threadIdx.x;
    if (i < n4) {
        float4 v = in[i];
        v.x = f2tf_f(v.x); v.y = f2tf_f(v.y);
        v.z = f2tf_f(v.z); v.w = f2tf_f(v.w);
        out[i] = v;
    }
}

// ---------------- LoRA A projection (+optional tf32 copy of X) ----------------
__global__ void lora_a_kernel(const float* __restrict__ X,
                              const float* __restrict__ Aw,
                              float* __restrict__ out,
                              float* __restrict__ Xr) {
    __shared__ float As[LORA_R * D_EMBED];
    for (int i = threadIdx.x; i < LORA_R * D_EMBED; i += blockDim.x) As[i] = Aw[i];
    __syncthreads();
    int warp = threadIdx.x >> 5, lane = threadIdx.x & 31;
    int row = blockIdx.x * 8 + warp;
    const float* xr = X + (size_t)row * D_EMBED;
    bool doCopy = (Xr != nullptr);
    float* xw = doCopy ? (Xr + (size_t)row * D_EMBED) : nullptr;
    float s[LORA_R];
#pragma unroll
    for (int r = 0; r < LORA_R; r++) s[r] = 0.f;
    for (int k = lane; k < D_EMBED; k += 32) {
        float xv = xr[k];
        if (doCopy) xw[k] = f2tf_f(xv);
#pragma unroll
        for (int r = 0; r < LORA_R; r++) s[r] += xv * As[r * D_EMBED + k];
    }
#pragma unroll
    for (int off = 16; off > 0; off >>= 1) {
#pragma unroll
        for (int r = 0; r < LORA_R; r++) s[r] += __shfl_xor_sync(0xffffffffu, s[r], off);
    }
    if (lane == 0) {
#pragma unroll
        for (int r = 0; r < LORA_R; r++) out[(size_t)row * LORA_R + r] = s[r];
    }
}

// ---------------- TF32 GEMM (NT) + LoRA + optional fused RoPE/round epilogue ----------------
// 128x128 tile, BK=32, 256 threads = 8 warps (4m x 2n), warp tile 32x64.
// doRope=1 (QKV GEMM): rows are tokens (s = row mod SEQ), each warp's 64 cols
// = one head; rotate (i, i+32) register pairs for q/k, then tf32-round all.
#define GP 36
__global__ __launch_bounds__(256) void gemm_tf32_lora(
    const float* __restrict__ A, const float* __restrict__ W,
    const float* __restrict__ XA, const float* __restrict__ LB,
    const float* __restrict__ bias, float* __restrict__ C,
    int M, int N, int K, int hasBias, int doRope) {
    extern __shared__ float smg[];
    float* As = smg;                    // [2][128*GP]
    float* Bs = smg + 2 * 128 * GP;     // [2][128*GP]

    int bm = blockIdx.y * 128, bn = blockIdx.x * 128;
    int tid = threadIdx.x;
    int warp = tid >> 5, lane = tid & 31;
    int wm = warp >> 1, wn = warp & 1;
    int qid = lane >> 2, qt = lane & 3;

    float acc[2][8][4];
#pragma unroll
    for (int mi = 0; mi < 2; mi++)
#pragma unroll
        for (int f = 0; f < 8; f++)
#pragma unroll
            for (int c = 0; c < 4; c++) acc[mi][f][c] = 0.f;

    auto issue_tiles = [&](int k0, int buf) {
#pragma unroll
        for (int c = tid; c < 1024; c += 256) {
            int row = c >> 3, off = (c & 7) * 4;
            cp16(As + buf * 128 * GP + row * GP + off,
                 A + (size_t)(bm + row) * K + k0 + off);
        }
#pragma unroll
        for (int c = tid; c < 1024; c += 256) {
            int row = c >> 3, off = (c & 7) * 4;
            cp16(Bs + buf * 128 * GP + row * GP + off,
                 W + (size_t)(bn + row) * K + k0 + off);
        }
    };

    issue_tiles(0, 0);
    CP_COMMIT();

    int niter = K >> 5;
    for (int it = 0; it < niter; it++) {
        int buf = it & 1;
        CP_WAIT0();
        __syncthreads();   // buf arrived AND all warps done reading buf (prev use)
        if (it + 1 < niter) { issue_tiles((it + 1) << 5, buf ^ 1); CP_COMMIT(); }

        const float* Ab = As + buf * 128 * GP;
        const float* Bb = Bs + buf * 128 * GP;
#pragma unroll
        for (int kk = 0; kk < 32; kk += 8) {
            uint32_t a[2][4];
#pragma unroll
            for (int mi = 0; mi < 2; mi++) {
                int m = wm * 32 + mi * 16 + qid;
                a[mi][0] = __float_as_uint(Ab[m * GP + kk + qt]);
                a[mi][1] = __float_as_uint(Ab[(m + 8) * GP + kk + qt]);
                a[mi][2] = __float_as_uint(Ab[m * GP + kk + qt + 4]);
                a[mi][3] = __float_as_uint(Ab[(m + 8) * GP + kk + qt + 4]);
            }
#pragma unroll
            for (int f = 0; f < 8; f++) {
                int n = wn * 64 + f * 8 + qid;
                uint32_t b0 = __float_as_uint(Bb[n * GP + kk + qt]);
                uint32_t b1 = __float_as_uint(Bb[n * GP + kk + qt + 4]);
                mma_tf32(acc[0][f], a[0][0], a[0][1], a[0][2], a[0][3], b0, b1);
                mma_tf32(acc[1][f], a[1][0], a[1][1], a[1][2], a[1][3], b0, b1);
            }
        }
        // no trailing barrier: next loop-top __syncthreads orders reads vs refill
    }

    // LoRA rank-8: acc += scale * XA[row,:] . LB[col,:]
    int r0[2], r1[2];
#pragma unroll
    for (int mi = 0; mi < 2; mi++) {
        r0[mi] = bm + wm * 32 + mi * 16 + qid;
        r1[mi] = r0[mi] + 8;
    }
#pragma unroll
    for (int rr = 0; rr < LORA_R; rr++) {
        float xa0[2], xa1[2];
#pragma unroll
        for (int mi = 0; mi < 2; mi++) {
            xa0[mi] = XA[(size_t)r0[mi] * LORA_R + rr] * LORA_SCALE_C;
            xa1[mi] = XA[(size_t)r1[mi] * LORA_R + rr] * LORA_SCALE_C;
        }
#pragma unroll
        for (int f = 0; f < 8; f++) {
            int c0 = bn + wn * 64 + f * 8 + 2 * qt;
            float lb0 = LB[(size_t)c0 * LORA_R + rr];
            float lb1 = LB[(size_t)(c0 + 1) * LORA_R + rr];
#pragma unroll
            for (int mi = 0; mi < 2; mi++) {
                acc[mi][f][0] += xa0[mi] * lb0;
                acc[mi][f][1] += xa0[mi] * lb1;
                acc[mi][f][2] += xa1[mi] * lb0;
                acc[mi][f][3] += xa1[mi] * lb1;
            }
        }
    }
    if (hasBias) {
#pragma unroll
        for (int f = 0; f < 8; f++) {
            int c0 = bn + wn * 64 + f * 8 + 2 * qt;
            float b0 = bias[c0], b1 = bias[c0 + 1];
#pragma unroll
            for (int mi = 0; mi < 2; mi++) {
                acc[mi][f][0] += b0; acc[mi][f][1] += b1;
                acc[mi][f][2] += b0; acc[mi][f][3] += b1;
            }
        }
    }

    // ---- fused RoPE + tf32 rounding (QKV GEMM only) ----
    if (doRope) {
        int sel = (bn + wn * 64) >> 10;      // 0=q, 1=k, 2=v (warp-uniform)
        if (sel < 2) {
            const float lf = logf(10000.f) / 32.f;
            float invf[4][2];
#pragma unroll
            for (int f = 0; f < 4; f++)
#pragma unroll
                for (int d = 0; d < 2; d++)
                    invf[f][d] = expf(-(float)(f * 8 + 2 * qt + d) * lf);
#pragma unroll
            for (int mi = 0; mi < 2; mi++) {
                int srow[2] = { r0[mi] & (SEQ - 1), r1[mi] & (SEQ - 1) };
#pragma unroll
                for (int f = 0; f < 4; f++) {
#pragma unroll
                    for (int c = 0; c < 4; c++) {
                        float ang = (float)srow[c >> 1] * invf[f][c & 1];
                        float sn, cs;
                        sincosf(ang, &sn, &cs);
                        float x0 = acc[mi][f][c], x1 = acc[mi][f + 4][c];
                        acc[mi][f][c]     = x0 * cs - x1 * sn;
                        acc[mi][f + 4][c] = x1 * cs + x0 * sn;
                    }
                }
            }
        }
#pragma unroll
        for (int mi = 0; mi < 2; mi++)
#pragma unroll
            for (int f = 0; f < 8; f++)
#pragma unroll
                for (int c = 0; c < 4; c++)
                    acc[mi][f][c] = f2tf_f(acc[mi][f][c]);
    }

#pragma unroll
    for (int mi = 0; mi < 2; mi++)
#pragma unroll
        for (int f = 0; f < 8; f++) {
            int c0 = bn + wn * 64 + f * 8 + 2 * qt;
            *(float2*)(C + (size_t)r0[mi] * N + c0) = make_float2(acc[mi][f][0], acc[mi][f][1]);
            *(float2*)(C + (size_t)r1[mi] * N + c0) = make_float2(acc[mi][f][2], acc[mi][f][3]);
        }
}

// ---------------- TF32 causal flash attention ----------------
// Br=128, Bc=64, hd=64; 256 threads = 8 warps, 16 q-rows per warp.
// q/k/v already roped + tf32-rounded; epilogue writes tf32-rounded attn.
#define FP 72
__global__ __launch_bounds__(256, 2) void flash_tf32(const float* __restrict__ qkv,
                                                     float* __restrict__ out) {
    extern __shared__ float sm[];
    float* Ks = sm;                       // [2][64*FP]
    float* Vs = sm + 2 * 64 * FP;         // [2][64*FP]
    float* Ps = sm + 4 * 64 * FP;         // 8 warps x [16][68]

    int qb = (int)gridDim.x - 1 - (int)blockIdx.x;   // heavy blocks first
    int bh = blockIdx.y;
    int b = bh >> 4, h = bh & 15;
    int q0 = qb * 128;
    int tid = threadIdx.x, warp = tid >> 5, lane = tid & 31;
    int qid = lane >> 2, qt = lane & 3;
    float* Pw = Ps + warp * 16 * 68;

    int gq0 = q0 + warp * 16 + qid;      // global q rows owned by this thread
    int gq1 = gq0 + 8;
    int wrow0 = q0 + warp * 16;          // smallest q row in warp
    int ntiles = 2 * qb + 2;

    auto issue_kv = [&](int jt, int buf) {
        const float* kbase = qkv + ((size_t)(b * SEQ + jt * 64) * 3 + 1) * D_EMBED + h * HDIM;
        const float* vbase = kbase + D_EMBED;
#pragma unroll
        for (int c = tid; c < 1024; c += 256) {
            int row = c >> 4, off = (c & 15) * 4;
            cp16(Ks + buf * 64 * FP + row * FP + off, kbase + (size_t)row * 3 * D_EMBED + off);
        }
#pragma unroll
        for (int c = tid; c < 1024; c += 256) {
            int row = c >> 4, off = (c & 15) * 4;
            cp16(Vs + buf * 64 * FP + row * FP + off, vbase + (size_t)row * 3 * D_EMBED + off);
        }
    };

    issue_kv(0, 0);
    CP_COMMIT();

    // ---- Q fragments straight from gmem; already tf32 bits, 0.125x is exact
    uint32_t qa[8][4];
    {
        const float sc = 0.125f;  // fold hd^-0.5 into Q (power of 2: exact)
        const float* qp0 = qkv + ((size_t)(b * SEQ + gq0) * 3) * D_EMBED + h * HDIM;
        const float* qp1 = qp0 + (size_t)8 * 3 * D_EMBED;
#pragma unroll
        for (int kk = 0; kk < 8; kk++) {
            qa[kk][0] = __float_as_uint(sc * __ldg(qp0 + kk * 8 + qt));
            qa[kk][1] = __float_as_uint(sc * __ldg(qp1 + kk * 8 + qt));
            qa[kk][2] = __float_as_uint(sc * __ldg(qp0 + kk * 8 + qt + 4));
            qa[kk][3] = __float_as_uint(sc * __ldg(qp1 + kk * 8 + qt + 4));
        }
    }

    float m0r = -1e30f, m1r = -1e30f, l0 = 0.f, l1 = 0.f;
    float o[8][4];
#pragma unroll
    for (int f = 0; f < 8; f++)
#pragma unroll
        for (int c = 0; c < 4; c++) o[f][c] = 0.f;

    for (int jt = 0; jt < ntiles; jt++) {
        int buf = jt & 1;
        CP_WAIT0();
        __syncthreads();                 // buf visible to all; prev compute done
        if (jt + 1 < ntiles) { issue_kv(jt + 1, buf ^ 1); CP_COMMIT(); }

        if (jt * 64 > wrow0 + 15) continue;   // tile fully masked for this warp

        const float* Kb = Ks + buf * 64 * FP;
        const float* Vb = Vs + buf * 64 * FP;

        // ---- S = Q K^T (per warp: 16 x 64)
        float s[8][4];
#pragma unroll
        for (int f = 0; f < 8; f++)
#pragma unroll
            for (int c = 0; c < 4; c++) s[f][c] = 0.f;
#pragma unroll
        for (int kk = 0; kk < 8; kk++) {
#pragma unroll
            for (int f = 0; f < 8; f++) {
                uint32_t b0 = __float_as_uint(Kb[(f * 8 + qid) * FP + kk * 8 + qt]);
                uint32_t b1 = __float_as_uint(Kb[(f * 8 + qid) * FP + kk * 8 + qt + 4]);
                mma_tf32(s[f], qa[kk][0], qa[kk][1], qa[kk][2], qa[kk][3], b0, b1);
            }
        }

        // ---- causal mask (only when tile reaches past warp's smallest row)
        if (jt * 64 + 63 > wrow0) {
#pragma unroll
            for (int f = 0; f < 8; f++) {
                int lc = jt * 64 + f * 8 + 2 * qt;
                if (lc > gq0)     s[f][0] = -1e30f;
                if (lc + 1 > gq0) s[f][1] = -1e30f;
                if (lc > gq1)     s[f][2] = -1e30f;
                if (lc + 1 > gq1) s[f][3] = -1e30f;
            }
        }

        // ---- online softmax (rows are quad-shared)
        float rm0 = -1e30f, rm1 = -1e30f;
#pragma unroll
        for (int f = 0; f < 8; f++) {
            rm0 = fmaxf(rm0, fmaxf(s[f][0], s[f][1]));
            rm1 = fmaxf(rm1, fmaxf(s[f][2], s[f][3]));
        }
        rm0 = fmaxf(rm0, __shfl_xor_sync(0xffffffffu, rm0, 1));
        rm0 = fmaxf(rm0, __shfl_xor_sync(0xffffffffu, rm0, 2));
        rm1 = fmaxf(rm1, __shfl_xor_sync(0xffffffffu, rm1, 1));
        rm1 = fmaxf(rm1, __shfl_xor_sync(0xffffffffu, rm1, 2));

        float mn0 = fmaxf(m0r, rm0), mn1 = fmaxf(m1r, rm1);
        float al0 = __expf(m0r - mn0), al1 = __expf(m1r - mn1);
        float rs0 = 0.f, rs1 = 0.f;
#pragma unroll
        for (int f = 0; f < 8; f++) {
            s[f][0] = __expf(s[f][0] - mn0);
            s[f][1] = __expf(s[f][1] - mn0);
            s[f][2] = __expf(s[f][2] - mn1);
            s[f][3] = __expf(s[f][3] - mn1);
            rs0 += s[f][0] + s[f][1];
            rs1 += s[f][2] + s[f][3];
        }
        rs0 += __shfl_xor_sync(0xffffffffu, rs0, 1);
        rs0 += __shfl_xor_sync(0xffffffffu, rs0, 2);
        rs1 += __shfl_xor_sync(0xffffffffu, rs1, 1);
        rs1 += __shfl_xor_sync(0xffffffffu, rs1, 2);
        l0 = l0 * al0 + rs0;
        l1 = l1 * al1 + rs1;
        m0r = mn0; m1r = mn1;
#pragma unroll
        for (int f = 0; f < 8; f++) {
            o[f][0] *= al0; o[f][1] *= al0;
            o[f][2] *= al1; o[f][3] *= al1;
        }

        // ---- stage P (tf32 bits) in per-warp smem, then PV mma into O
        __syncwarp();
#pragma unroll
        for (int f = 0; f < 8; f++) {
            float2 p0 = make_float2(f2tf_f(s[f][0]), f2tf_f(s[f][1]));
            float2 p1 = make_float2(f2tf_f(s[f][2]), f2tf_f(s[f][3]));
            *(float2*)(Pw + qid * 68 + f * 8 + 2 * qt) = p0;
            *(float2*)(Pw + (qid + 8) * 68 + f * 8 + 2 * qt) = p1;
        }
        __syncwarp();
#pragma unroll
        for (int kk = 0; kk < 8; kk++) {
            uint32_t pa0 = __float_as_uint(Pw[qid * 68 + kk * 8 + qt]);
            uint32_t pa1 = __float_as_uint(Pw[(qid + 8) * 68 + kk * 8 + qt]);
            uint32_t pa2 = __float_as_uint(Pw[qid * 68 + kk * 8 + qt + 4]);
            uint32_t pa3 = __float_as_uint(Pw[(qid + 8) * 68 + kk * 8 + qt + 4]);
#pragma unroll
            for (int f = 0; f < 8; f++) {
                uint32_t b0 = __float_as_uint(Vb[(kk * 8 + qt) * FP + f * 8 + qid]);
                uint32_t b1 = __float_as_uint(Vb[(kk * 8 + qt + 4) * FP + f * 8 + qid]);
                mma_tf32(o[f], pa0, pa1, pa2, pa3, b0, b1);
            }
        }
    }

    // ---- epilogue: normalize, round to tf32 (proj GEMM A operand), write
    float inv0 = 1.f / l0, inv1 = 1.f / l1;
    size_t ro = (size_t)(b * SEQ + gq0) * D_EMBED + h * HDIM;
#pragma unroll
    for (int f = 0; f < 8; f++) {
        *(float2*)(out + ro + f * 8 + 2 * qt) =
            make_float2(f2tf_f(o[f][0] * inv0), f2tf_f(o[f][1] * inv0));
        *(float2*)(out + ro + 8 * D_EMBED + f * 8 + 2 * qt) =
            make_float2(f2tf_f(o[f][2] * inv1), f2tf_f(o[f][3] * inv1));
    }
}

// ---------------- launcher ----------------
extern "C" void kernel_launch(void* const* d_in, const int* in_sizes, int n_in,
                              void* d_out, int out_size) {
    const float* x     = (const float*)d_in[0];
    const float* Wqkv  = (const float*)d_in[1];
    const float* Aqkv  = (const float*)d_in[2];
    const float* Bqkv  = (const float*)d_in[3];
    const float* Wproj = (const float*)d_in[4];
    const float* bproj = (const float*)d_in[5];
    const float* Aproj = (const float*)d_in[6];
    const float* Bproj = (const float*)d_in[7];

    float *qkv, *attn, *xa, *xr, *wqr, *wpr;
    cudaGetSymbolAddress((void**)&qkv,  g_qkv);
    cudaGetSymbolAddress((void**)&attn, g_attn);
    cudaGetSymbolAddress((void**)&xa,   g_xa);
    cudaGetSymbolAddress((void**)&xr,   g_xr);
    cudaGetSymbolAddress((void**)&wqr,  g_wqr);
    cudaGetSymbolAddress((void**)&wpr,  g_wpr);

    int gsmem = 4 * 128 * GP * (int)sizeof(float);          // 73.7 KB
    cudaFuncSetAttribute(gemm_tf32_lora,
                         cudaFuncAttributeMaxDynamicSharedMemorySize, gsmem);
    int fsmem = (4 * 64 * FP + 8 * 16 * 68) * (int)sizeof(float);  // 108.5 KB
    cudaFuncSetAttribute(flash_tf32,
                         cudaFuncAttributeMaxDynamicSharedMemorySize, fsmem);

    // 0) tf32 pre-rounding of weights
    {
        int n4q = 3 * D_EMBED * D_EMBED / 4;
        round_tf32_kernel<<<(n4q + 255) / 256, 256>>>((const float4*)Wqkv, (float4*)wqr, n4q);
        int n4p = D_EMBED * D_EMBED / 4;
        round_tf32_kernel<<<(n4p + 255) / 256, 256>>>((const float4*)Wproj, (float4*)wpr, n4p);
    }
    // 1) LoRA-A for qkv (fp32 x) + tf32 copy of x
    lora_a_kernel<<<NTOK / 8, 256>>>(x, Aqkv, xa, xr);
    // 2) QKV GEMM + LoRA-B + fused RoPE + tf32 rounding
    gemm_tf32_lora<<<dim3(3 * D_EMBED / 128, NTOK / 128), 256, gsmem>>>(
        xr, wqr, xa, Bqkv, nullptr, qkv, NTOK, 3 * D_EMBED, D_EMBED, 0, 1);
    // 3) causal flash attention (tf32, cp.async), Br=128
    flash_tf32<<<dim3(SEQ / 128, BATCH * NHEAD), 256, fsmem>>>(qkv, attn);
    // 4) LoRA-A for proj (attn is tf32-rounded)
    lora_a_kernel<<<NTOK / 8, 256>>>(attn, Aproj, xa, nullptr);
    // 5) output projection + bias + LoRA-B -> d_out
    gemm_tf32_lora<<<dim3(D_EMBED / 128, NTOK / 128), 256, gsmem>>>(
        attn, wpr, xa, Bproj, bproj, (float*)d_out, NTOK, D_EMBED, D_EMBED, 1, 0);
}

// round 14
// speedup vs baseline: 1.1219x; 1.1219x over previous
#include <cuda_runtime.h>
#include <math.h>
#include <stdint.h>

#define D_EMBED 1024
#define SEQ     2048
#define BATCH   2
#define NHEAD   16
#define HDIM    64
#define NTOK    (BATCH * SEQ)      // 4096
#define LORA_R  8
#define LORA_SCALE_C 2.0f          // alpha/r = 16/8

// ---------------- scratch (no allocations allowed) ----------------
__device__ float g_qkv[(size_t)NTOK * 3 * D_EMBED];   // [B,S,3,H,hd] (roped+rounded)
__device__ float g_attn[(size_t)NTOK * D_EMBED];      // attention out (tf32-rounded)
__device__ float g_xa[(size_t)NTOK * LORA_R];         // x @ A^T
__device__ float g_xr[(size_t)NTOK * D_EMBED];        // tf32-rounded x
__device__ float g_wqr[(size_t)3 * D_EMBED * D_EMBED];// tf32-rounded Wqkv
__device__ float g_wpr[(size_t)D_EMBED * D_EMBED];    // tf32-rounded Wproj

// ---------------- helpers ----------------
__device__ __forceinline__ uint32_t f2tf(float x) {
    uint32_t u; asm("cvt.rna.tf32.f32 %0, %1;" : "=r"(u) : "f"(x)); return u;
}
__device__ __forceinline__ float f2tf_f(float x) {
    return __uint_as_float(f2tf(x));
}
__device__ __forceinline__ void mma_tf32(float c[4],
                                         uint32_t a0, uint32_t a1, uint32_t a2, uint32_t a3,
                                         uint32_t b0, uint32_t b1) {
    asm volatile(
        "mma.sync.aligned.m16n8k8.row.col.f32.tf32.tf32.f32 "
        "{%0,%1,%2,%3}, {%4,%5,%6,%7}, {%8,%9}, {%0,%1,%2,%3};"
        : "+f"(c[0]), "+f"(c[1]), "+f"(c[2]), "+f"(c[3])
        : "r"(a0), "r"(a1), "r"(a2), "r"(a3), "r"(b0), "r"(b1));
}
__device__ __forceinline__ void cp16(float* dst_smem, const float* src) {
    uint32_t d = (uint32_t)__cvta_generic_to_shared(dst_smem);
    asm volatile("cp.async.cg.shared.global [%0], [%1], 16;" :: "r"(d), "l"(src));
}
#define CP_COMMIT() asm volatile("cp.async.commit_group;")
#define CP_WAIT0()  asm volatile("cp.async.wait_group 0;")

// ---------------- tf32 pre-round (weights) ----------------
__global__ void round_tf32_kernel(const float4* __restrict__ in,
                                  float4* __restrict__ out, int n4) {
    int i = blockIdx.x * blockDim.x + threadIdx.x;
    if (i < n4) {
        float4 v = in[i];
        v.x = f2tf_f(v.x); v.y = f2tf_f(v.y);
        v.z = f2tf_f(v.z); v.w = f2tf_f(v.w);
        out[i] = v;
    }
}

// ---------------- LoRA A projection (+optional tf32 copy of X) ----------------
__global__ void lora_a_kernel(const float* __restrict__ X,
                              const float* __restrict__ Aw,
                              float* __restrict__ out,
                              float* __restrict__ Xr) {
    __shared__ float As[LORA_R * D_EMBED];
    for (int i = threadIdx.x; i < LORA_R * D_EMBED; i += blockDim.x) As[i] = Aw[i];
    __syncthreads();
    int warp = threadIdx.x >> 5, lane = threadIdx.x & 31;
    int row = blockIdx.x * 8 + warp;
    const float* xr = X + (size_t)row * D_EMBED;
    bool doCopy = (Xr != nullptr);
    float* xw = doCopy ? (Xr + (size_t)row * D_EMBED) : nullptr;
    float s[LORA_R];
#pragma unroll
    for (int r = 0; r < LORA_R; r++) s[r] = 0.f;
    for (int k = lane; k < D_EMBED; k += 32) {
        float xv = xr[k];
        if (doCopy) xw[k] = f2tf_f(xv);
#pragma unroll
        for (int r = 0; r < LORA_R; r++) s[r] += xv * As[r * D_EMBED + k];
    }
#pragma unroll
    for (int off = 16; off > 0; off >>= 1) {
#pragma unroll
        for (int r = 0; r < LORA_R; r++) s[r] += __shfl_xor_sync(0xffffffffu, s[r], off);
    }
    if (lane == 0) {
#pragma unroll
        for (int r = 0; r < LORA_R; r++) out[(size_t)row * LORA_R + r] = s[r];
    }
}

// ---------------- TF32 GEMM (NT) + LoRA + optional fused RoPE/round epilogue ----------------
// 128x128 tile, BK=32, 256 threads = 8 warps (4m x 2n), warp tile 32x64.
// __launch_bounds__(256, 2): cap regs at 128 so 2 CTAs/SM fit (R13 lesson:
// the RoPE epilogue pushed regs to 139 -> 1 CTA/SM -> big regression).
#define GP 36
__global__ __launch_bounds__(256, 2) void gemm_tf32_lora(
    const float* __restrict__ A, const float* __restrict__ W,
    const float* __restrict__ XA, const float* __restrict__ LB,
    const float* __restrict__ bias, float* __restrict__ C,
    int M, int N, int K, int hasBias, int doRope) {
    extern __shared__ float smg[];
    float* As = smg;                    // [2][128*GP]
    float* Bs = smg + 2 * 128 * GP;     // [2][128*GP]

    int bm = blockIdx.y * 128, bn = blockIdx.x * 128;
    int tid = threadIdx.x;
    int warp = tid >> 5, lane = tid & 31;
    int wm = warp >> 1, wn = warp & 1;
    int qid = lane >> 2, qt = lane & 3;

    float acc[2][8][4];
#pragma unroll
    for (int mi = 0; mi < 2; mi++)
#pragma unroll
        for (int f = 0; f < 8; f++)
#pragma unroll
            for (int c = 0; c < 4; c++) acc[mi][f][c] = 0.f;

    auto issue_tiles = [&](int k0, int buf) {
#pragma unroll
        for (int c = tid; c < 1024; c += 256) {
            int row = c >> 3, off = (c & 7) * 4;
            cp16(As + buf * 128 * GP + row * GP + off,
                 A + (size_t)(bm + row) * K + k0 + off);
        }
#pragma unroll
        for (int c = tid; c < 1024; c += 256) {
            int row = c >> 3, off = (c & 7) * 4;
            cp16(Bs + buf * 128 * GP + row * GP + off,
                 W + (size_t)(bn + row) * K + k0 + off);
        }
    };

    issue_tiles(0, 0);
    CP_COMMIT();

    int niter = K >> 5;
    for (int it = 0; it < niter; it++) {
        int buf = it & 1;
        CP_WAIT0();
        __syncthreads();   // buf arrived AND all warps done reading buf (prev use)
        if (it + 1 < niter) { issue_tiles((it + 1) << 5, buf ^ 1); CP_COMMIT(); }

        const float* Ab = As + buf * 128 * GP;
        const float* Bb = Bs + buf * 128 * GP;
#pragma unroll
        for (int kk = 0; kk < 32; kk += 8) {
            uint32_t a[2][4];
#pragma unroll
            for (int mi = 0; mi < 2; mi++) {
                int m = wm * 32 + mi * 16 + qid;
                a[mi][0] = __float_as_uint(Ab[m * GP + kk + qt]);
                a[mi][1] = __float_as_uint(Ab[(m + 8) * GP + kk + qt]);
                a[mi][2] = __float_as_uint(Ab[m * GP + kk + qt + 4]);
                a[mi][3] = __float_as_uint(Ab[(m + 8) * GP + kk + qt + 4]);
            }
#pragma unroll
            for (int f = 0; f < 8; f++) {
                int n = wn * 64 + f * 8 + qid;
                uint32_t b0 = __float_as_uint(Bb[n * GP + kk + qt]);
                uint32_t b1 = __float_as_uint(Bb[n * GP + kk + qt + 4]);
                mma_tf32(acc[0][f], a[0][0], a[0][1], a[0][2], a[0][3], b0, b1);
                mma_tf32(acc[1][f], a[1][0], a[1][1], a[1][2], a[1][3], b0, b1);
            }
        }
        // no trailing barrier: next loop-top __syncthreads orders reads vs refill
    }

    // LoRA rank-8: acc += scale * XA[row,:] . LB[col,:]
    int r0[2], r1[2];
#pragma unroll
    for (int mi = 0; mi < 2; mi++) {
        r0[mi] = bm + wm * 32 + mi * 16 + qid;
        r1[mi] = r0[mi] + 8;
    }
#pragma unroll
    for (int rr = 0; rr < LORA_R; rr++) {
        float xa0[2], xa1[2];
#pragma unroll
        for (int mi = 0; mi < 2; mi++) {
            xa0[mi] = XA[(size_t)r0[mi] * LORA_R + rr] * LORA_SCALE_C;
            xa1[mi] = XA[(size_t)r1[mi] * LORA_R + rr] * LORA_SCALE_C;
        }
#pragma unroll
        for (int f = 0; f < 8; f++) {
            int c0 = bn + wn * 64 + f * 8 + 2 * qt;
            float lb0 = LB[(size_t)c0 * LORA_R + rr];
            float lb1 = LB[(size_t)(c0 + 1) * LORA_R + rr];
#pragma unroll
            for (int mi = 0; mi < 2; mi++) {
                acc[mi][f][0] += xa0[mi] * lb0;
                acc[mi][f][1] += xa0[mi] * lb1;
                acc[mi][f][2] += xa1[mi] * lb0;
                acc[mi][f][3] += xa1[mi] * lb1;
            }
        }
    }
    if (hasBias) {
#pragma unroll
        for (int f = 0; f < 8; f++) {
            int c0 = bn + wn * 64 + f * 8 + 2 * qt;
            float b0 = bias[c0], b1 = bias[c0 + 1];
#pragma unroll
            for (int mi = 0; mi < 2; mi++) {
                acc[mi][f][0] += b0; acc[mi][f][1] += b1;
                acc[mi][f][2] += b0; acc[mi][f][3] += b1;
            }
        }
    }

    // ---- fused RoPE + tf32 rounding (QKV GEMM only) ----
    if (doRope) {
        int sel = (bn + wn * 64) >> 10;      // 0=q, 1=k, 2=v (warp-uniform)
        if (sel < 2) {
            const float lf = logf(10000.f) / 32.f;
#pragma unroll
            for (int mi = 0; mi < 2; mi++) {
                int srow[2] = { r0[mi] & (SEQ - 1), r1[mi] & (SEQ - 1) };
#pragma unroll
                for (int f = 0; f < 4; f++) {
#pragma unroll
                    for (int c = 0; c < 4; c++) {
                        float invf = expf(-(float)(f * 8 + 2 * qt + (c & 1)) * lf);
                        float ang = (float)srow[c >> 1] * invf;
                        float sn, cs;
                        sincosf(ang, &sn, &cs);
                        float x0 = acc[mi][f][c], x1 = acc[mi][f + 4][c];
                        acc[mi][f][c]     = x0 * cs - x1 * sn;
                        acc[mi][f + 4][c] = x1 * cs + x0 * sn;
                    }
                }
            }
        }
#pragma unroll
        for (int mi = 0; mi < 2; mi++)
#pragma unroll
            for (int f = 0; f < 8; f++)
#pragma unroll
                for (int c = 0; c < 4; c++)
                    acc[mi][f][c] = f2tf_f(acc[mi][f][c]);
    }

#pragma unroll
    for (int mi = 0; mi < 2; mi++)
#pragma unroll
        for (int f = 0; f < 8; f++) {
            int c0 = bn + wn * 64 + f * 8 + 2 * qt;
            *(float2*)(C + (size_t)r0[mi] * N + c0) = make_float2(acc[mi][f][0], acc[mi][f][1]);
            *(float2*)(C + (size_t)r1[mi] * N + c0) = make_float2(acc[mi][f][2], acc[mi][f][3]);
        }
}

// ---------------- TF32 causal flash attention ----------------
// Br=128, Bc=64, hd=64; 256 threads = 8 warps, 16 q-rows per warp.
// q/k/v already roped + tf32-rounded; epilogue writes tf32-rounded attn.
#define FP 72
__global__ __launch_bounds__(256, 2) void flash_tf32(const float* __restrict__ qkv,
                                                     float* __restrict__ out) {
    extern __shared__ float sm[];
    float* Ks = sm;                       // [2][64*FP]
    float* Vs = sm + 2 * 64 * FP;         // [2][64*FP]
    float* Ps = sm + 4 * 64 * FP;         // 8 warps x [16][68]

    int qb = (int)gridDim.x - 1 - (int)blockIdx.x;   // heavy blocks first
    int bh = blockIdx.y;
    int b = bh >> 4, h = bh & 15;
    int q0 = qb * 128;
    int tid = threadIdx.x, warp = tid >> 5, lane = tid & 31;
    int qid = lane >> 2, qt = lane & 3;
    float* Pw = Ps + warp * 16 * 68;

    int gq0 = q0 + warp * 16 + qid;      // global q rows owned by this thread
    int gq1 = gq0 + 8;
    int wrow0 = q0 + warp * 16;          // smallest q row in warp
    int ntiles = 2 * qb + 2;

    auto issue_kv = [&](int jt, int buf) {
        const float* kbase = qkv + ((size_t)(b * SEQ + jt * 64) * 3 + 1) * D_EMBED + h * HDIM;
        const float* vbase = kbase + D_EMBED;
#pragma unroll
        for (int c = tid; c < 1024; c += 256) {
            int row = c >> 4, off = (c & 15) * 4;
            cp16(Ks + buf * 64 * FP + row * FP + off, kbase + (size_t)row * 3 * D_EMBED + off);
        }
#pragma unroll
        for (int c = tid; c < 1024; c += 256) {
            int row = c >> 4, off = (c & 15) * 4;
            cp16(Vs + buf * 64 * FP + row * FP + off, vbase + (size_t)row * 3 * D_EMBED + off);
        }
    };

    issue_kv(0, 0);
    CP_COMMIT();

    // ---- Q fragments straight from gmem; already tf32 bits, 0.125x is exact
    uint32_t qa[8][4];
    {
        const float sc = 0.125f;  // fold hd^-0.5 into Q (power of 2: exact)
        const float* qp0 = qkv + ((size_t)(b * SEQ + gq0) * 3) * D_EMBED + h * HDIM;
        const float* qp1 = qp0 + (size_t)8 * 3 * D_EMBED;
#pragma unroll
        for (int kk = 0; kk < 8; kk++) {
            qa[kk][0] = __float_as_uint(sc * __ldg(qp0 + kk * 8 + qt));
            qa[kk][1] = __float_as_uint(sc * __ldg(qp1 + kk * 8 + qt));
            qa[kk][2] = __float_as_uint(sc * __ldg(qp0 + kk * 8 + qt + 4));
            qa[kk][3] = __float_as_uint(sc * __ldg(qp1 + kk * 8 + qt + 4));
        }
    }

    float m0r = -1e30f, m1r = -1e30f, l0 = 0.f, l1 = 0.f;
    float o[8][4];
#pragma unroll
    for (int f = 0; f < 8; f++)
#pragma unroll
        for (int c = 0; c < 4; c++) o[f][c] = 0.f;

    for (int jt = 0; jt < ntiles; jt++) {
        int buf = jt & 1;
        CP_WAIT0();
        __syncthreads();                 // buf visible to all; prev compute done
        if (jt + 1 < ntiles) { issue_kv(jt + 1, buf ^ 1); CP_COMMIT(); }

        if (jt * 64 > wrow0 + 15) continue;   // tile fully masked for this warp

        const float* Kb = Ks + buf * 64 * FP;
        const float* Vb = Vs + buf * 64 * FP;

        // ---- S = Q K^T (per warp: 16 x 64)
        float s[8][4];
#pragma unroll
        for (int f = 0; f < 8; f++)
#pragma unroll
            for (int c = 0; c < 4; c++) s[f][c] = 0.f;
#pragma unroll
        for (int kk = 0; kk < 8; kk++) {
#pragma unroll
            for (int f = 0; f < 8; f++) {
                uint32_t b0 = __float_as_uint(Kb[(f * 8 + qid) * FP + kk * 8 + qt]);
                uint32_t b1 = __float_as_uint(Kb[(f * 8 + qid) * FP + kk * 8 + qt + 4]);
                mma_tf32(s[f], qa[kk][0], qa[kk][1], qa[kk][2], qa[kk][3], b0, b1);
            }
        }

        // ---- causal mask (only when tile reaches past warp's smallest row)
        if (jt * 64 + 63 > wrow0) {
#pragma unroll
            for (int f = 0; f < 8; f++) {
                int lc = jt * 64 + f * 8 + 2 * qt;
                if (lc > gq0)     s[f][0] = -1e30f;
                if (lc + 1 > gq0) s[f][1] = -1e30f;
                if (lc > gq1)     s[f][2] = -1e30f;
                if (lc + 1 > gq1) s[f][3] = -1e30f;
            }
        }

        // ---- online softmax (rows are quad-shared)
        float rm0 = -1e30f, rm1 = -1e30f;
#pragma unroll
        for (int f = 0; f < 8; f++) {
            rm0 = fmaxf(rm0, fmaxf(s[f][0], s[f][1]));
            rm1 = fmaxf(rm1, fmaxf(s[f][2], s[f][3]));
        }
        rm0 = fmaxf(rm0, __shfl_xor_sync(0xffffffffu, rm0, 1));
        rm0 = fmaxf(rm0, __shfl_xor_sync(0xffffffffu, rm0, 2));
        rm1 = fmaxf(rm1, __shfl_xor_sync(0xffffffffu, rm1, 1));
        rm1 = fmaxf(rm1, __shfl_xor_sync(0xffffffffu, rm1, 2));

        float mn0 = fmaxf(m0r, rm0), mn1 = fmaxf(m1r, rm1);
        float al0 = __expf(m0r - mn0), al1 = __expf(m1r - mn1);
        float rs0 = 0.f, rs1 = 0.f;
#pragma unroll
        for (int f = 0; f < 8; f++) {
            s[f][0] = __expf(s[f][0] - mn0);
            s[f][1] = __expf(s[f][1] - mn0);
            s[f][2] = __expf(s[f][2] - mn1);
            s[f][3] = __expf(s[f][3] - mn1);
            rs0 += s[f][0] + s[f][1];
            rs1 += s[f][2] + s[f][3];
        }
        rs0 += __shfl_xor_sync(0xffffffffu, rs0, 1);
        rs0 += __shfl_xor_sync(0xffffffffu, rs0, 2);
        rs1 += __shfl_xor_sync(0xffffffffu, rs1, 1);
        rs1 += __shfl_xor_sync(0xffffffffu, rs1, 2);
        l0 = l0 * al0 + rs0;
        l1 = l1 * al1 + rs1;
        m0r = mn0; m1r = mn1;
#pragma unroll
        for (int f = 0; f < 8; f++) {
            o[f][0] *= al0; o[f][1] *= al0;
            o[f][2] *= al1; o[f][3] *= al1;
        }

        // ---- stage P (tf32 bits) in per-warp smem, then PV mma into O
        __syncwarp();
#pragma unroll
        for (int f = 0; f < 8; f++) {
            float2 p0 = make_float2(f2tf_f(s[f][0]), f2tf_f(s[f][1]));
            float2 p1 = make_float2(f2tf_f(s[f][2]), f2tf_f(s[f][3]));
            *(float2*)(Pw + qid * 68 + f * 8 + 2 * qt) = p0;
            *(float2*)(Pw + (qid + 8) * 68 + f * 8 + 2 * qt) = p1;
        }
        __syncwarp();
#pragma unroll
        for (int kk = 0; kk < 8; kk++) {
            uint32_t pa0 = __float_as_uint(Pw[qid * 68 + kk * 8 + qt]);
            uint32_t pa1 = __float_as_uint(Pw[(qid + 8) * 68 + kk * 8 + qt]);
            uint32_t pa2 = __float_as_uint(Pw[qid * 68 + kk * 8 + qt + 4]);
            uint32_t pa3 = __float_as_uint(Pw[(qid + 8) * 68 + kk * 8 + qt + 4]);
#pragma unroll
            for (int f = 0; f < 8; f++) {
                uint32_t b0 = __float_as_uint(Vb[(kk * 8 + qt) * FP + f * 8 + qid]);
                uint32_t b1 = __float_as_uint(Vb[(kk * 8 + qt + 4) * FP + f * 8 + qid]);
                mma_tf32(o[f], pa0, pa1, pa2, pa3, b0, b1);
            }
        }
    }

    // ---- epilogue: normalize, round to tf32 (proj GEMM A operand), write
    float inv0 = 1.f / l0, inv1 = 1.f / l1;
    size_t ro = (size_t)(b * SEQ + gq0) * D_EMBED + h * HDIM;
#pragma unroll
    for (int f = 0; f < 8; f++) {
        *(float2*)(out + ro + f * 8 + 2 * qt) =
            make_float2(f2tf_f(o[f][0] * inv0), f2tf_f(o[f][1] * inv0));
        *(float2*)(out + ro + 8 * D_EMBED + f * 8 + 2 * qt) =
            make_float2(f2tf_f(o[f][2] * inv1), f2tf_f(o[f][3] * inv1));
    }
}

// ---------------- launcher ----------------
extern "C" void kernel_launch(void* const* d_in, const int* in_sizes, int n_in,
                              void* d_out, int out_size) {
    const float* x     = (const float*)d_in[0];
    const float* Wqkv  = (const float*)d_in[1];
    const float* Aqkv  = (const float*)d_in[2];
    const float* Bqkv  = (const float*)d_in[3];
    const float* Wproj = (const float*)d_in[4];
    const float* bproj = (const float*)d_in[5];
    const float* Aproj = (const float*)d_in[6];
    const float* Bproj = (const float*)d_in[7];

    float *qkv, *attn, *xa, *xr, *wqr, *wpr;
    cudaGetSymbolAddress((void**)&qkv,  g_qkv);
    cudaGetSymbolAddress((void**)&attn, g_attn);
    cudaGetSymbolAddress((void**)&xa,   g_xa);
    cudaGetSymbolAddress((void**)&xr,   g_xr);
    cudaGetSymbolAddress((void**)&wqr,  g_wqr);
    cudaGetSymbolAddress((void**)&wpr,  g_wpr);

    int gsmem = 4 * 128 * GP * (int)sizeof(float);          // 73.7 KB
    cudaFuncSetAttribute(gemm_tf32_lora,
                         cudaFuncAttributeMaxDynamicSharedMemorySize, gsmem);
    int fsmem = (4 * 64 * FP + 8 * 16 * 68) * (int)sizeof(float);  // 108.5 KB
    cudaFuncSetAttribute(flash_tf32,
                         cudaFuncAttributeMaxDynamicSharedMemorySize, fsmem);

    // 0) tf32 pre-rounding of weights
    {
        int n4q = 3 * D_EMBED * D_EMBED / 4;
        round_tf32_kernel<<<(n4q + 255) / 256, 256>>>((const float4*)Wqkv, (float4*)wqr, n4q);
        int n4p = D_EMBED * D_EMBED / 4;
        round_tf32_kernel<<<(n4p + 255) / 256, 256>>>((const float4*)Wproj, (float4*)wpr, n4p);
    }
    // 1) LoRA-A for qkv (fp32 x) + tf32 copy of x
    lora_a_kernel<<<NTOK / 8, 256>>>(x, Aqkv, xa, xr);
    // 2) QKV GEMM + LoRA-B + fused RoPE + tf32 rounding
    gemm_tf32_lora<<<dim3(3 * D_EMBED / 128, NTOK / 128), 256, gsmem>>>(
        xr, wqr, xa, Bqkv, nullptr, qkv, NTOK, 3 * D_EMBED, D_EMBED, 0, 1);
    // 3) causal flash attention (tf32, cp.async), Br=128
    flash_tf32<<<dim3(SEQ / 128, BATCH * NHEAD), 256, fsmem>>>(qkv, attn);
    // 4) LoRA-A for proj (attn is tf32-rounded)
    lora_a_kernel<<<NTOK / 8, 256>>>(attn, Aproj, xa, nullptr);
    // 5) output projection + bias + LoRA-B -> d_out
    gemm_tf32_lora<<<dim3(D_EMBED / 128, NTOK / 128), 256, gsmem>>>(
        attn, wpr, xa, Bproj, bproj, (float*)d_out, NTOK, D_EMBED, D_EMBED, 1, 0);
}